// round 15
// baseline (speedup 1.0000x reference)
#include <cuda_runtime.h>
#include <cuda_bf16.h>
#include <cstdint>

#define NDV 100000
#define NE  800000
#define H   128
#define OD  40
#define SCB 98        // scan blocks of 1024

// ---------------- device scratch (static globals: allocation-free) -------------
__device__ float g_out[(size_t)NDV * H];
__device__ float g_p  [(size_t)NDV * OD];
__device__ uint4 g_ahi4[(size_t)NDV * 16];  // self operand hi (128 bf16 = 16 uint4/node)
__device__ uint4 g_alo4[(size_t)NDV * 16];  // self operand lo
__device__ uint4 g_agh4[(size_t)NDV * 16];  // neigh (agg) hi
__device__ uint4 g_agl4[(size_t)NDV * 16];  // neigh (agg) lo
__device__ int   g_degi[NDV];
__device__ int   g_rowstart[NDV + 1];
__device__ int   g_cursor[NDV];
__device__ int   g_csr_src[NE];
__device__ int   g_bsum[SCB];
__device__ float g_sum[H];      // zero at load; k_bnfin re-zeroes after consuming
__device__ float g_sq [H];
__device__ float g_scale[H];
__device__ float g_shift[H];

// ---------------- helpers ------------------------------------------------------
__device__ __forceinline__ uint32_t s2u(const void* p) {
    uint32_t a;
    asm("{ .reg .u64 t; cvta.to.shared.u64 t, %1; cvt.u32.u64 %0, t; }" : "=r"(a) : "l"(p));
    return a;
}
__device__ __forceinline__ uint32_t pkbf(float a, float b) {
    __nv_bfloat162 t = __halves2bfloat162(__float2bfloat16(a), __float2bfloat16(b));
    return *(uint32_t*)&t;
}
__device__ __forceinline__ float bflo(float x) {
    __nv_bfloat16 h = __float2bfloat16(x);
    return x - __bfloat162float(h);
}
__device__ __forceinline__ float2 up2(uint32_t u) {
    __nv_bfloat162 b = *(__nv_bfloat162*)&u;
    return __bfloat1622float2(b);
}
__device__ __forceinline__ void ldmA(uint32_t* r, uint32_t a) {
    asm volatile("ldmatrix.sync.aligned.m8n8.x4.shared.b16 {%0,%1,%2,%3},[%4];"
                 : "=r"(r[0]), "=r"(r[1]), "=r"(r[2]), "=r"(r[3]) : "r"(a));
}
__device__ __forceinline__ void ldmBT(uint32_t* r, uint32_t a) {
    asm volatile("ldmatrix.sync.aligned.m8n8.x4.trans.shared.b16 {%0,%1,%2,%3},[%4];"
                 : "=r"(r[0]), "=r"(r[1]), "=r"(r[2]), "=r"(r[3]) : "r"(a));
}
__device__ __forceinline__ void mmabf(float* d, const uint32_t* a, const uint32_t* b) {
    asm volatile("mma.sync.aligned.m16n8k16.row.col.f32.bf16.bf16.f32 "
                 "{%0,%1,%2,%3},{%4,%5,%6,%7},{%8,%9},{%0,%1,%2,%3};"
                 : "+f"(d[0]), "+f"(d[1]), "+f"(d[2]), "+f"(d[3])
                 : "r"(a[0]), "r"(a[1]), "r"(a[2]), "r"(a[3]), "r"(b[0]), "r"(b[1]));
}

// ---------------- feat -> hi/lo split, + zero degi ------------------------------
__global__ void k_cvtz(const float* __restrict__ feat) {
    int i = blockIdx.x * blockDim.x + threadIdx.x;
    if (i < NDV) g_degi[i] = 0;
    if (i >= NDV * 16) return;
    float4 a = ((const float4*)feat)[2 * i];
    float4 b = ((const float4*)feat)[2 * i + 1];
    g_ahi4[i] = make_uint4(pkbf(a.x, a.y), pkbf(a.z, a.w), pkbf(b.x, b.y), pkbf(b.z, b.w));
    g_alo4[i] = make_uint4(pkbf(bflo(a.x), bflo(a.y)), pkbf(bflo(a.z), bflo(a.w)),
                           pkbf(bflo(b.x), bflo(b.y)), pkbf(bflo(b.z), bflo(b.w)));
}

// ---------------- CSR build ----------------------------------------------------
__global__ void k_degi(const int* __restrict__ dst) {
    int e = blockIdx.x * blockDim.x + threadIdx.x;
    if (e < NE) atomicAdd(&g_degi[dst[e]], 1);
}
__global__ __launch_bounds__(1024) void k_scan1() {
    __shared__ int sh[32];
    int t = threadIdx.x, i = blockIdx.x * 1024 + t;
    int v = (i < NDV) ? g_degi[i] : 0;
    #pragma unroll
    for (int o = 16; o > 0; o >>= 1) v += __shfl_down_sync(0xffffffffu, v, o);
    if ((t & 31) == 0) sh[t >> 5] = v;
    __syncthreads();
    if (t < 32) {
        int u = sh[t];
        #pragma unroll
        for (int o = 16; o > 0; o >>= 1) u += __shfl_down_sync(0xffffffffu, u, o);
        if (t == 0) g_bsum[blockIdx.x] = u;
    }
}
// block-local exclusive scan; block offset computed in-kernel (scan2 merged)
__global__ __launch_bounds__(1024) void k_scan3() {
    __shared__ int wsum[32];
    __shared__ int boffs;
    int t = threadIdx.x, lane = t & 31, w = t >> 5;
    int i = blockIdx.x * 1024 + t;
    int v = (i < NDV) ? g_degi[i] : 0;
    int s = v;
    #pragma unroll
    for (int o = 1; o < 32; o <<= 1) {
        int u = __shfl_up_sync(0xffffffffu, s, o);
        if (lane >= o) s += u;
    }
    if (lane == 31) wsum[w] = s;
    if (w == 1) {   // warp 1 reduces bsum[0..blockIdx.x)
        int acc = 0;
        for (int j = lane; j < (int)blockIdx.x; j += 32) acc += g_bsum[j];
        #pragma unroll
        for (int o = 16; o > 0; o >>= 1) acc += __shfl_down_sync(0xffffffffu, acc, o);
        if (lane == 0) boffs = acc;
    }
    __syncthreads();
    if (t < 32) {
        int u = wsum[t];
        #pragma unroll
        for (int o = 1; o < 32; o <<= 1) {
            int x = __shfl_up_sync(0xffffffffu, u, o);
            if (t >= o) u += x;
        }
        wsum[t] = u;
    }
    __syncthreads();
    int excl = s - v + (w > 0 ? wsum[w - 1] : 0) + boffs;
    if (i < NDV) { g_rowstart[i] = excl; g_cursor[i] = excl; }
    if (i == NDV - 1) g_rowstart[NDV] = excl + v;
}
__global__ void k_scatter(const int* __restrict__ src, const int* __restrict__ dst) {
    int e = blockIdx.x * blockDim.x + threadIdx.x;
    if (e >= NE) return;
    int pos = atomicAdd(&g_cursor[dst[e]], 1);
    g_csr_src[pos] = src[e];
}

// ---- CSR mean-aggregation: warp per node, 4-edge-batched gathers ---------------
// layer 0: reads feat fp32; layer 1: reconstructs hi+lo. Writes agg hi/lo.
__global__ void k_aggcsr(const float* __restrict__ feat, int use_hl) {
    int idx = blockIdx.x * blockDim.x + threadIdx.x;
    int n = idx >> 5, lane = idx & 31;
    if (n >= NDV) return;
    int b = g_rowstart[n], e = g_rowstart[n + 1];
    float4 acc = make_float4(0.f, 0.f, 0.f, 0.f);
    if (!use_hl) {
        int i = b;
        for (; i + 4 <= e; i += 4) {
            int s0 = g_csr_src[i], s1 = g_csr_src[i + 1];
            int s2 = g_csr_src[i + 2], s3 = g_csr_src[i + 3];
            float4 v0 = ((const float4*)(feat + (size_t)s0 * H))[lane];
            float4 v1 = ((const float4*)(feat + (size_t)s1 * H))[lane];
            float4 v2 = ((const float4*)(feat + (size_t)s2 * H))[lane];
            float4 v3 = ((const float4*)(feat + (size_t)s3 * H))[lane];
            acc.x += (v0.x + v1.x) + (v2.x + v3.x);
            acc.y += (v0.y + v1.y) + (v2.y + v3.y);
            acc.z += (v0.z + v1.z) + (v2.z + v3.z);
            acc.w += (v0.w + v1.w) + (v2.w + v3.w);
        }
        for (; i < e; ++i) {
            int s = g_csr_src[i];
            float4 v = ((const float4*)(feat + (size_t)s * H))[lane];
            acc.x += v.x; acc.y += v.y; acc.z += v.z; acc.w += v.w;
        }
    } else {
        int i = b;
        for (; i + 4 <= e; i += 4) {
            int sI[4];
            #pragma unroll
            for (int j = 0; j < 4; ++j) sI[j] = g_csr_src[i + j];
            uint2 hh[4], ll[4];
            #pragma unroll
            for (int j = 0; j < 4; ++j) {
                hh[j] = ((const uint2*)(g_ahi4 + (size_t)sI[j] * 16))[lane];
                ll[j] = ((const uint2*)(g_alo4 + (size_t)sI[j] * 16))[lane];
            }
            #pragma unroll
            for (int j = 0; j < 4; ++j) {
                float2 h0 = up2(hh[j].x), h1 = up2(hh[j].y);
                float2 l0 = up2(ll[j].x), l1 = up2(ll[j].y);
                acc.x += h0.x + l0.x; acc.y += h0.y + l0.y;
                acc.z += h1.x + l1.x; acc.w += h1.y + l1.y;
            }
        }
        for (; i < e; ++i) {
            int s = g_csr_src[i];
            uint2 hh = ((const uint2*)(g_ahi4 + (size_t)s * 16))[lane];
            uint2 ll = ((const uint2*)(g_alo4 + (size_t)s * 16))[lane];
            float2 h0 = up2(hh.x), h1 = up2(hh.y);
            float2 l0 = up2(ll.x), l1 = up2(ll.y);
            acc.x += h0.x + l0.x; acc.y += h0.y + l0.y;
            acc.z += h1.x + l1.x; acc.w += h1.y + l1.y;
        }
    }
    float iv = 1.f / fmaxf((float)(e - b), 1.f);
    acc.x *= iv; acc.y *= iv; acc.z *= iv; acc.w *= iv;
    ((uint2*)(g_agh4 + (size_t)n * 16))[lane] = make_uint2(pkbf(acc.x, acc.y), pkbf(acc.z, acc.w));
    ((uint2*)(g_agl4 + (size_t)n * 16))[lane] =
        make_uint2(pkbf(bflo(acc.x), bflo(acc.y)), pkbf(bflo(acc.z), bflo(acc.w)));
}

// ================= layers 0/1 GEMM (copy-only staging from hi/lo buffers) ======
#define T64 ((NDV + 63) >> 6)
#define MM_BHI 0
#define MM_BLO 65536
#define MM_AHI 131072
#define MM_ALO 163840
#define MM_STAT 196608
#define MM_TOT (196608 + 1024)

__global__ __launch_bounds__(256, 1)
void k_gemm01mma(const float* __restrict__ Wself, const float* __restrict__ Wneigh) {
    extern __shared__ char smem[];
    uint32_t sb = s2u(smem);
    float* ssum = (float*)(smem + MM_STAT);
    float* ssq  = ssum + H;
    const int tid = threadIdx.x, lane = tid & 31, wid = tid >> 5;

    for (int it = 0; it < 16; ++it) {
        int idx = tid + (it << 8);
        int k = idx >> 4, nc = idx & 15, n0 = nc << 3;
        const float* wsrc = (k < 128) ? (Wself + k * H + n0) : (Wneigh + (k - 128) * H + n0);
        float4 v0 = *(const float4*)(wsrc);
        float4 v1 = *(const float4*)(wsrc + 4);
        uint32_t off = (uint32_t)k * 256 + (uint32_t)((nc ^ (k & 7)) << 4);
        *(uint4*)(smem + MM_BHI + off) = make_uint4(
            pkbf(v0.x, v0.y), pkbf(v0.z, v0.w), pkbf(v1.x, v1.y), pkbf(v1.z, v1.w));
        *(uint4*)(smem + MM_BLO + off) = make_uint4(
            pkbf(bflo(v0.x), bflo(v0.y)), pkbf(bflo(v0.z), bflo(v0.w)),
            pkbf(bflo(v1.x), bflo(v1.y)), pkbf(bflo(v1.z), bflo(v1.w)));
    }
    if (tid < H) { ssum[tid] = 0.f; ssq[tid] = 0.f; }
    __syncthreads();

    const int wm = wid & 1, wn = wid >> 1;
    const int rbase = wm << 5, nbase = wn << 5;
    const int l7 = lane & 7, kp = lane >> 4, l15 = lane & 15;
    const int g = lane >> 2, tq = lane & 3;
    const uint32_t aRowHi = sb + MM_AHI + (uint32_t)(rbase + l15) * 512;
    const uint32_t aRowLo = aRowHi + (MM_ALO - MM_AHI);
    const int nb0 = (nbase >> 3) + kp;
    const uint32_t bch0 = (uint32_t)((nb0 ^ l7) << 4);
    const uint32_t bch1 = (uint32_t)(((nb0 + 2) ^ l7) << 4);
    const uint32_t bHiBase = sb + MM_BHI + (uint32_t)l15 * 256;
    const uint32_t bLoBase = sb + MM_BLO + (uint32_t)l15 * 256;

    const int srow = tid >> 2, skq = (tid & 3) << 6;   // k-base 0/64/128/192
    const bool selfHalf = skq < 128;
    const int chunk0 = selfHalf ? (skq >> 3) : ((skq - 128) >> 3);   // 0 or 8
    float csum[8], csq[8];
    #pragma unroll
    for (int i = 0; i < 8; ++i) { csum[i] = 0.f; csq[i] = 0.f; }

    uint4 pre[16];
    auto do_prefetch = [&](int t0p) {
        int rowg = t0p + srow;
        bool valid = rowg < NDV;
        const uint4* hs = (selfHalf ? g_ahi4 : g_agh4) + (size_t)rowg * 16 + chunk0;
        const uint4* ls = (selfHalf ? g_alo4 : g_agl4) + (size_t)rowg * 16 + chunk0;
        #pragma unroll
        for (int j = 0; j < 8; ++j) {
            pre[j]     = valid ? hs[j] : make_uint4(0u, 0u, 0u, 0u);
            pre[8 + j] = valid ? ls[j] : make_uint4(0u, 0u, 0u, 0u);
        }
    };

    do_prefetch(blockIdx.x << 6);

    for (int t = blockIdx.x; t < T64; t += gridDim.x) {
        int t0 = t << 6;
        __syncthreads();
        // ---- copy prefetched chunks -> smem (pure STS.128) ----
        {
            uint32_t rowoff = (uint32_t)srow * 512;
            int rs = srow & 7;
            #pragma unroll
            for (int j = 0; j < 8; ++j) {
                int k8 = (skq >> 3) + j;                   // 0..31
                uint32_t off = rowoff + (uint32_t)((k8 ^ rs) << 4);
                *(uint4*)(smem + MM_AHI + off) = pre[j];
                *(uint4*)(smem + MM_ALO + off) = pre[8 + j];
            }
        }
        __syncthreads();
        int tn = t + gridDim.x;
        if (tn < T64) do_prefetch(tn << 6);

        float d[2][4][4];
        #pragma unroll
        for (int m = 0; m < 2; ++m)
            #pragma unroll
            for (int nb = 0; nb < 4; ++nb)
                #pragma unroll
                for (int e = 0; e < 4; ++e) d[m][nb][e] = 0.f;

        #pragma unroll 4
        for (int ks = 0; ks < 16; ++ks) {
            uint32_t ach = (uint32_t)((((ks << 1) + kp) ^ l7) << 4);
            uint32_t ahi0[4], ahi1[4], alo0[4], alo1[4];
            ldmA(ahi0, aRowHi + ach);
            ldmA(ahi1, aRowHi + 8192 + ach);
            ldmA(alo0, aRowLo + ach);
            ldmA(alo1, aRowLo + 8192 + ach);
            uint32_t bks = (uint32_t)ks << 12;
            uint32_t bh0[4], bh1[4], bl0[4], bl1[4];
            ldmBT(bh0, bHiBase + bks + bch0);
            ldmBT(bh1, bHiBase + bks + bch1);
            ldmBT(bl0, bLoBase + bks + bch0);
            ldmBT(bl1, bLoBase + bks + bch1);
            mmabf(d[0][0], ahi0, bh0); mmabf(d[0][1], ahi0, bh0 + 2);
            mmabf(d[0][2], ahi0, bh1); mmabf(d[0][3], ahi0, bh1 + 2);
            mmabf(d[1][0], ahi1, bh0); mmabf(d[1][1], ahi1, bh0 + 2);
            mmabf(d[1][2], ahi1, bh1); mmabf(d[1][3], ahi1, bh1 + 2);
            mmabf(d[0][0], ahi0, bl0); mmabf(d[0][1], ahi0, bl0 + 2);
            mmabf(d[0][2], ahi0, bl1); mmabf(d[0][3], ahi0, bl1 + 2);
            mmabf(d[1][0], ahi1, bl0); mmabf(d[1][1], ahi1, bl0 + 2);
            mmabf(d[1][2], ahi1, bl1); mmabf(d[1][3], ahi1, bl1 + 2);
            mmabf(d[0][0], alo0, bh0); mmabf(d[0][1], alo0, bh0 + 2);
            mmabf(d[0][2], alo0, bh1); mmabf(d[0][3], alo0, bh1 + 2);
            mmabf(d[1][0], alo1, bh0); mmabf(d[1][1], alo1, bh0 + 2);
            mmabf(d[1][2], alo1, bh1); mmabf(d[1][3], alo1, bh1 + 2);
        }

        #pragma unroll
        for (int m = 0; m < 2; ++m) {
            int row0 = t0 + rbase + (m << 4) + g;
            int row1 = row0 + 8;
            if (row0 < NDV) {
                float* o = g_out + (size_t)row0 * H + nbase + (tq << 1);
                #pragma unroll
                for (int nb = 0; nb < 4; ++nb) {
                    *(float2*)(o + (nb << 3)) = make_float2(d[m][nb][0], d[m][nb][1]);
                    csum[nb * 2 + 0] += d[m][nb][0]; csq[nb * 2 + 0] += d[m][nb][0] * d[m][nb][0];
                    csum[nb * 2 + 1] += d[m][nb][1]; csq[nb * 2 + 1] += d[m][nb][1] * d[m][nb][1];
                }
            }
            if (row1 < NDV) {
                float* o = g_out + (size_t)row1 * H + nbase + (tq << 1);
                #pragma unroll
                for (int nb = 0; nb < 4; ++nb) {
                    *(float2*)(o + (nb << 3)) = make_float2(d[m][nb][2], d[m][nb][3]);
                    csum[nb * 2 + 0] += d[m][nb][2]; csq[nb * 2 + 0] += d[m][nb][2] * d[m][nb][2];
                    csum[nb * 2 + 1] += d[m][nb][3]; csq[nb * 2 + 1] += d[m][nb][3] * d[m][nb][3];
                }
            }
        }
    }

    #pragma unroll
    for (int nb = 0; nb < 4; ++nb)
        #pragma unroll
        for (int j = 0; j < 2; ++j) {
            int col = nbase + (tq << 1) + (nb << 3) + j;
            atomicAdd(&ssum[col], csum[nb * 2 + j]);
            atomicAdd(&ssq[col],  csq[nb * 2 + j]);
        }
    __syncthreads();
    if (tid < H) {
        atomicAdd(&g_sum[tid], ssum[tid]);
        atomicAdd(&g_sq[tid],  ssq[tid]);
    }
}

// consumes stats AND re-zeroes them (replay-invariant)
__global__ void k_bnfin(const float* __restrict__ gamma, const float* __restrict__ beta) {
    int c = threadIdx.x;
    float mean = g_sum[c] * (1.f / NDV);
    float var  = g_sq[c]  * (1.f / NDV) - mean * mean;
    float sc = gamma[c] * rsqrtf(var + 1e-5f);
    g_scale[c] = sc;
    g_shift[c] = beta[c] - mean * sc;
    g_sum[c] = 0.f;
    g_sq[c]  = 0.f;
}

// BN+ReLU then split to hi/lo (8 elems per thread)
__global__ void k_apply() {
    int i = blockIdx.x * blockDim.x + threadIdx.x;
    if (i >= NDV * 16) return;
    int c8 = i & 15;
    float4 a = ((const float4*)g_out)[2 * i];
    float4 b = ((const float4*)g_out)[2 * i + 1];
    float4 sca = ((const float4*)g_scale)[c8 * 2], scb = ((const float4*)g_scale)[c8 * 2 + 1];
    float4 sha = ((const float4*)g_shift)[c8 * 2], shb = ((const float4*)g_shift)[c8 * 2 + 1];
    a.x = fmaxf(fmaf(a.x, sca.x, sha.x), 0.f);
    a.y = fmaxf(fmaf(a.y, sca.y, sha.y), 0.f);
    a.z = fmaxf(fmaf(a.z, sca.z, sha.z), 0.f);
    a.w = fmaxf(fmaf(a.w, sca.w, sha.w), 0.f);
    b.x = fmaxf(fmaf(b.x, scb.x, shb.x), 0.f);
    b.y = fmaxf(fmaf(b.y, scb.y, shb.y), 0.f);
    b.z = fmaxf(fmaf(b.z, scb.z, shb.z), 0.f);
    b.w = fmaxf(fmaf(b.w, scb.w, shb.w), 0.f);
    g_ahi4[i] = make_uint4(pkbf(a.x, a.y), pkbf(a.z, a.w), pkbf(b.x, b.y), pkbf(b.z, b.w));
    g_alo4[i] = make_uint4(pkbf(bflo(a.x), bflo(a.y)), pkbf(bflo(a.z), bflo(a.w)),
                           pkbf(bflo(b.x), bflo(b.y)), pkbf(bflo(b.z), bflo(b.w)));
}

// ================= layer 2 GEMM (copy-only staging from hi/lo buffers) =========
#define M2_BHI 0
#define M2_BLO 32768
#define M2_AHI 65536
#define M2_ALO 81920
#define M2_TOT 98304

__global__ __launch_bounds__(256, 1)
void k_gemm2mma(const float* __restrict__ Wself, const float* __restrict__ Wneigh,
                const float* __restrict__ bias, float* __restrict__ out) {
    extern __shared__ char smem[];
    uint32_t sb = s2u(smem);
    const int tid = threadIdx.x, lane = tid & 31, wid = tid >> 5;

    for (int it = 0; it < 8; ++it) {
        int idx = tid + (it << 8);
        int k = idx >> 4, nc = idx & 15, n0 = nc << 3;
        float4 v0 = make_float4(0.f, 0.f, 0.f, 0.f), v1 = v0;
        if (n0 < 40) {
            const float* w = Wself + k * OD + n0;
            v0 = *(const float4*)(w); v1 = *(const float4*)(w + 4);
        } else if (n0 < 80) {
            const float* w = Wneigh + k * OD + (n0 - 40);
            v0 = *(const float4*)(w); v1 = *(const float4*)(w + 4);
        }
        uint32_t off = (uint32_t)k * 256 + (uint32_t)((nc ^ (k & 7)) << 4);
        *(uint4*)(smem + M2_BHI + off) = make_uint4(
            pkbf(v0.x, v0.y), pkbf(v0.z, v0.w), pkbf(v1.x, v1.y), pkbf(v1.z, v1.w));
        *(uint4*)(smem + M2_BLO + off) = make_uint4(
            pkbf(bflo(v0.x), bflo(v0.y)), pkbf(bflo(v0.z), bflo(v0.w)),
            pkbf(bflo(v1.x), bflo(v1.y)), pkbf(bflo(v1.z), bflo(v1.w)));
    }
    __syncthreads();

    const int wm = wid & 1, wn = wid >> 1;
    const int rbase = wm << 5, nbase = wn << 5;
    const int l7 = lane & 7, kp = lane >> 4, l15 = lane & 15;
    const int g = lane >> 2, tq = lane & 3;
    const uint32_t aRowHi = sb + M2_AHI + (uint32_t)(rbase + l15) * 256;
    const uint32_t aRowLo = aRowHi + (M2_ALO - M2_AHI);
    const int nb0 = (nbase >> 3) + kp;
    const uint32_t bch0 = (uint32_t)((nb0 ^ l7) << 4);
    const uint32_t bch1 = (uint32_t)(((nb0 + 2) ^ l7) << 4);
    const uint32_t bHiBase = sb + M2_BHI + (uint32_t)l15 * 256;
    const uint32_t bLoBase = sb + M2_BLO + (uint32_t)l15 * 256;

    const int srow = tid >> 2, skq = (tid & 3) << 5;   // 32 k per thread = 4 chunks

    for (int t = blockIdx.x; t < T64; t += gridDim.x) {
        int t0 = t << 6;
        __syncthreads();
        {
            int rowg = t0 + srow;
            bool valid = rowg < NDV;
            const uint4* hs = g_ahi4 + (size_t)rowg * 16 + (skq >> 3);
            const uint4* ls = g_alo4 + (size_t)rowg * 16 + (skq >> 3);
            uint32_t rowoff = (uint32_t)srow * 256;
            int rs = srow & 7;
            #pragma unroll
            for (int j = 0; j < 4; ++j) {
                int k8 = (skq >> 3) + j;                   // 0..15
                uint32_t off = rowoff + (uint32_t)((k8 ^ rs) << 4);
                *(uint4*)(smem + M2_AHI + off) = valid ? hs[j] : make_uint4(0u, 0u, 0u, 0u);
                *(uint4*)(smem + M2_ALO + off) = valid ? ls[j] : make_uint4(0u, 0u, 0u, 0u);
            }
        }
        __syncthreads();

        float d[2][4][4];
        #pragma unroll
        for (int m = 0; m < 2; ++m)
            #pragma unroll
            for (int nb = 0; nb < 4; ++nb)
                #pragma unroll
                for (int e = 0; e < 4; ++e) d[m][nb][e] = 0.f;

        #pragma unroll 4
        for (int ks = 0; ks < 8; ++ks) {
            uint32_t ach = (uint32_t)((((ks << 1) + kp) ^ l7) << 4);
            uint32_t ahi0[4], ahi1[4], alo0[4], alo1[4];
            ldmA(ahi0, aRowHi + ach);
            ldmA(ahi1, aRowHi + 4096 + ach);
            ldmA(alo0, aRowLo + ach);
            ldmA(alo1, aRowLo + 4096 + ach);
            uint32_t bks = (uint32_t)ks << 12;
            uint32_t bh0[4], bh1[4], bl0[4], bl1[4];
            ldmBT(bh0, bHiBase + bks + bch0);
            ldmBT(bh1, bHiBase + bks + bch1);
            ldmBT(bl0, bLoBase + bks + bch0);
            ldmBT(bl1, bLoBase + bks + bch1);
            mmabf(d[0][0], ahi0, bh0); mmabf(d[0][1], ahi0, bh0 + 2);
            mmabf(d[0][2], ahi0, bh1); mmabf(d[0][3], ahi0, bh1 + 2);
            mmabf(d[1][0], ahi1, bh0); mmabf(d[1][1], ahi1, bh0 + 2);
            mmabf(d[1][2], ahi1, bh1); mmabf(d[1][3], ahi1, bh1 + 2);
            mmabf(d[0][0], ahi0, bl0); mmabf(d[0][1], ahi0, bl0 + 2);
            mmabf(d[0][2], ahi0, bl1); mmabf(d[0][3], ahi0, bl1 + 2);
            mmabf(d[1][0], ahi1, bl0); mmabf(d[1][1], ahi1, bl0 + 2);
            mmabf(d[1][2], ahi1, bl1); mmabf(d[1][3], ahi1, bl1 + 2);
            mmabf(d[0][0], alo0, bh0); mmabf(d[0][1], alo0, bh0 + 2);
            mmabf(d[0][2], alo0, bh1); mmabf(d[0][3], alo0, bh1 + 2);
            mmabf(d[1][0], alo1, bh0); mmabf(d[1][1], alo1, bh0 + 2);
            mmabf(d[1][2], alo1, bh1); mmabf(d[1][3], alo1, bh1 + 2);
        }

        #pragma unroll
        for (int m = 0; m < 2; ++m) {
            int row0 = t0 + rbase + (m << 4) + g;
            int row1 = row0 + 8;
            #pragma unroll
            for (int nb = 0; nb < 4; ++nb) {
                int col = nbase + (tq << 1) + (nb << 3);
                #pragma unroll
                for (int j = 0; j < 2; ++j) {
                    int c = col + j;
                    if (c < 40) {
                        if (row0 < NDV) out[(size_t)row0 * OD + c] = d[m][nb][j] + bias[c];
                        if (row1 < NDV) out[(size_t)row1 * OD + c] = d[m][nb][j + 2] + bias[c];
                    } else if (c < 80) {
                        if (row0 < NDV) g_p[(size_t)row0 * OD + c - 40] = d[m][nb][j];
                        if (row1 < NDV) g_p[(size_t)row1 * OD + c - 40] = d[m][nb][j + 2];
                    }
                }
            }
        }
    }
}

// CSR layer-2 neighbor mean: 10 threads per node, 4-edge-batched p reads
__global__ void k_edge2csr(float* __restrict__ out) {
    int idx = blockIdx.x * blockDim.x + threadIdx.x;
    if (idx >= NDV * 10) return;
    int n = idx / 10, c4 = idx - n * 10;
    int b = g_rowstart[n], e = g_rowstart[n + 1];
    float4 acc = make_float4(0.f, 0.f, 0.f, 0.f);
    int i = b;
    for (; i + 4 <= e; i += 4) {
        int s0 = g_csr_src[i], s1 = g_csr_src[i + 1];
        int s2 = g_csr_src[i + 2], s3 = g_csr_src[i + 3];
        float4 v0 = *(const float4*)(g_p + (size_t)s0 * OD + c4 * 4);
        float4 v1 = *(const float4*)(g_p + (size_t)s1 * OD + c4 * 4);
        float4 v2 = *(const float4*)(g_p + (size_t)s2 * OD + c4 * 4);
        float4 v3 = *(const float4*)(g_p + (size_t)s3 * OD + c4 * 4);
        acc.x += (v0.x + v1.x) + (v2.x + v3.x);
        acc.y += (v0.y + v1.y) + (v2.y + v3.y);
        acc.z += (v0.z + v1.z) + (v2.z + v3.z);
        acc.w += (v0.w + v1.w) + (v2.w + v3.w);
    }
    for (; i < e; ++i) {
        int s = g_csr_src[i];
        float4 v = *(const float4*)(g_p + (size_t)s * OD + c4 * 4);
        acc.x += v.x; acc.y += v.y; acc.z += v.z; acc.w += v.w;
    }
    float iv = 1.f / fmaxf((float)(e - b), 1.f);
    float* o = out + (size_t)n * OD + c4 * 4;
    float4 cur = *(float4*)o;
    cur.x += acc.x * iv; cur.y += acc.y * iv;
    cur.z += acc.z * iv; cur.w += acc.w * iv;
    *(float4*)o = cur;
}

// ---------------- host launcher ------------------------------------------------
extern "C" void kernel_launch(void* const* d_in, const int* in_sizes, int n_in,
                              void* d_out, int out_size) {
    const float* feat = (const float*)d_in[0];
    const int*   src  = (const int*)d_in[1];
    const int*   dst  = (const int*)d_in[2];
    const float* Ws0 = (const float*)d_in[3];
    const float* Wn0 = (const float*)d_in[4];
    const float* ga0 = (const float*)d_in[5];
    const float* be0 = (const float*)d_in[6];
    const float* Ws1 = (const float*)d_in[7];
    const float* Wn1 = (const float*)d_in[8];
    const float* ga1 = (const float*)d_in[9];
    const float* be1 = (const float*)d_in[10];
    const float* Ws2 = (const float*)d_in[11];
    const float* Wn2 = (const float*)d_in[12];
    const float* b2  = (const float*)d_in[13];
    float* out = (float*)d_out;

    cudaFuncSetAttribute(k_gemm01mma, cudaFuncAttributeMaxDynamicSharedMemorySize, MM_TOT);
    cudaFuncSetAttribute(k_gemm2mma,  cudaFuncAttributeMaxDynamicSharedMemorySize, M2_TOT);

    const int TB = 256;
    // CSR build + feat split
    k_cvtz<<<(NDV * 16 + TB - 1) / TB, TB>>>(feat);
    k_degi<<<(NE + TB - 1) / TB, TB>>>(dst);
    k_scan1<<<SCB, 1024>>>();
    k_scan3<<<SCB, 1024>>>();
    k_scatter<<<(NE + TB - 1) / TB, TB>>>(src, dst);

    // ---- layer 0 ----
    k_aggcsr<<<(NDV * 32 + TB - 1) / TB, TB>>>(feat, 0);
    k_gemm01mma<<<148, 256, MM_TOT>>>(Ws0, Wn0);
    k_bnfin<<<1, 128>>>(ga0, be0);
    k_apply<<<(NDV * 16 + TB - 1) / TB, TB>>>();

    // ---- layer 1 ----
    k_aggcsr<<<(NDV * 32 + TB - 1) / TB, TB>>>(nullptr, 1);
    k_gemm01mma<<<148, 256, MM_TOT>>>(Ws1, Wn1);
    k_bnfin<<<1, 128>>>(ga1, be1);
    k_apply<<<(NDV * 16 + TB - 1) / TB, TB>>>();

    // ---- layer 2 ----
    k_gemm2mma<<<148, 256, M2_TOT>>>(Ws2, Wn2, b2, out);
    k_edge2csr<<<(NDV * 10 + TB - 1) / TB, TB>>>(out);

    (void)in_sizes; (void)n_in; (void)out_size;
}

// round 16
// speedup vs baseline: 1.0816x; 1.0816x over previous
#include <cuda_runtime.h>
#include <cuda_bf16.h>
#include <cstdint>

#define NDV 100000
#define NE  800000
#define H   128
#define OD  40
#define SCB 98        // scan blocks of 1024

// ---------------- device scratch (static globals: allocation-free) -------------
__device__ float g_agg[(size_t)NDV * H];
__device__ float g_out[(size_t)NDV * H];
__device__ float g_h  [(size_t)NDV * H];
__device__ float g_p  [(size_t)NDV * OD];
__device__ int   g_degi[NDV];
__device__ int   g_rowstart[NDV + 1];
__device__ int   g_cursor[NDV];
__device__ int   g_csr_src[NE];
__device__ int   g_bsum[SCB];
__device__ float g_sum[H];      // zero at load; k_bnfin re-zeroes after consuming
__device__ float g_sq [H];
__device__ float g_scale[H];
__device__ float g_shift[H];

// ---------------- helpers ------------------------------------------------------
__device__ __forceinline__ uint32_t s2u(const void* p) {
    uint32_t a;
    asm("{ .reg .u64 t; cvta.to.shared.u64 t, %1; cvt.u32.u64 %0, t; }" : "=r"(a) : "l"(p));
    return a;
}
__device__ __forceinline__ uint32_t pkbf(float a, float b) {
    __nv_bfloat162 t = __halves2bfloat162(__float2bfloat16(a), __float2bfloat16(b));
    return *(uint32_t*)&t;
}
__device__ __forceinline__ float bflo(float x) {
    __nv_bfloat16 h = __float2bfloat16(x);
    return x - __bfloat162float(h);
}
__device__ __forceinline__ void ldmA(uint32_t* r, uint32_t a) {
    asm volatile("ldmatrix.sync.aligned.m8n8.x4.shared.b16 {%0,%1,%2,%3},[%4];"
                 : "=r"(r[0]), "=r"(r[1]), "=r"(r[2]), "=r"(r[3]) : "r"(a));
}
__device__ __forceinline__ void ldmBT(uint32_t* r, uint32_t a) {
    asm volatile("ldmatrix.sync.aligned.m8n8.x4.trans.shared.b16 {%0,%1,%2,%3},[%4];"
                 : "=r"(r[0]), "=r"(r[1]), "=r"(r[2]), "=r"(r[3]) : "r"(a));
}
__device__ __forceinline__ void mmabf(float* d, const uint32_t* a, const uint32_t* b) {
    asm volatile("mma.sync.aligned.m16n8k16.row.col.f32.bf16.bf16.f32 "
                 "{%0,%1,%2,%3},{%4,%5,%6,%7},{%8,%9},{%0,%1,%2,%3};"
                 : "+f"(d[0]), "+f"(d[1]), "+f"(d[2]), "+f"(d[3])
                 : "r"(a[0]), "r"(a[1]), "r"(a[2]), "r"(a[3]), "r"(b[0]), "r"(b[1]));
}

// ---------------- CSR build ----------------------------------------------------
__global__ void k_zdegi() {
    int i = blockIdx.x * blockDim.x + threadIdx.x;
    if (i < NDV) g_degi[i] = 0;
}
__global__ void k_degi(const int* __restrict__ dst) {
    int e = blockIdx.x * blockDim.x + threadIdx.x;
    if (e < NE) atomicAdd(&g_degi[dst[e]], 1);
}
__global__ __launch_bounds__(1024) void k_scan1() {
    __shared__ int sh[32];
    int t = threadIdx.x, i = blockIdx.x * 1024 + t;
    int v = (i < NDV) ? g_degi[i] : 0;
    #pragma unroll
    for (int o = 16; o > 0; o >>= 1) v += __shfl_down_sync(0xffffffffu, v, o);
    if ((t & 31) == 0) sh[t >> 5] = v;
    __syncthreads();
    if (t < 32) {
        int u = sh[t];
        #pragma unroll
        for (int o = 16; o > 0; o >>= 1) u += __shfl_down_sync(0xffffffffu, u, o);
        if (t == 0) g_bsum[blockIdx.x] = u;
    }
}
// block-local exclusive scan; block offset computed in-kernel (merged scan2)
__global__ __launch_bounds__(1024) void k_scan3() {
    __shared__ int wsum[32];
    __shared__ int boffs;
    int t = threadIdx.x, lane = t & 31, w = t >> 5;
    int i = blockIdx.x * 1024 + t;
    int v = (i < NDV) ? g_degi[i] : 0;
    int s = v;
    #pragma unroll
    for (int o = 1; o < 32; o <<= 1) {
        int u = __shfl_up_sync(0xffffffffu, s, o);
        if (lane >= o) s += u;
    }
    if (lane == 31) wsum[w] = s;
    if (w == 1) {   // warp 1 reduces bsum[0..blockIdx.x)
        int acc = 0;
        for (int j = lane; j < (int)blockIdx.x; j += 32) acc += g_bsum[j];
        #pragma unroll
        for (int o = 16; o > 0; o >>= 1) acc += __shfl_down_sync(0xffffffffu, acc, o);
        if (lane == 0) boffs = acc;
    }
    __syncthreads();
    if (t < 32) {
        int u = wsum[t];
        #pragma unroll
        for (int o = 1; o < 32; o <<= 1) {
            int x = __shfl_up_sync(0xffffffffu, u, o);
            if (t >= o) u += x;
        }
        wsum[t] = u;
    }
    __syncthreads();
    int excl = s - v + (w > 0 ? wsum[w - 1] : 0) + boffs;
    if (i < NDV) { g_rowstart[i] = excl; g_cursor[i] = excl; }
    if (i == NDV - 1) g_rowstart[NDV] = excl + v;
}
__global__ void k_scatter(const int* __restrict__ src, const int* __restrict__ dst) {
    int e = blockIdx.x * blockDim.x + threadIdx.x;
    if (e >= NE) return;
    int pos = atomicAdd(&g_cursor[dst[e]], 1);
    g_csr_src[pos] = src[e];
}

// ---- CSR mean-aggregation: warp per node, 4-edge-batched gathers (MLP=4) ------
__global__ void k_aggcsr(const float* __restrict__ hext, int use_gh) {
    int idx = blockIdx.x * blockDim.x + threadIdx.x;
    int n = idx >> 5, lane = idx & 31;
    if (n >= NDV) return;
    const float* h = use_gh ? (const float*)g_h : hext;
    int b = g_rowstart[n], e = g_rowstart[n + 1];
    float4 acc = make_float4(0.f, 0.f, 0.f, 0.f);
    int i = b;
    for (; i + 4 <= e; i += 4) {
        int s0 = g_csr_src[i], s1 = g_csr_src[i + 1];
        int s2 = g_csr_src[i + 2], s3 = g_csr_src[i + 3];
        float4 v0 = ((const float4*)(h + (size_t)s0 * H))[lane];
        float4 v1 = ((const float4*)(h + (size_t)s1 * H))[lane];
        float4 v2 = ((const float4*)(h + (size_t)s2 * H))[lane];
        float4 v3 = ((const float4*)(h + (size_t)s3 * H))[lane];
        acc.x += (v0.x + v1.x) + (v2.x + v3.x);
        acc.y += (v0.y + v1.y) + (v2.y + v3.y);
        acc.z += (v0.z + v1.z) + (v2.z + v3.z);
        acc.w += (v0.w + v1.w) + (v2.w + v3.w);
    }
    for (; i < e; ++i) {
        int s = g_csr_src[i];
        float4 v = ((const float4*)(h + (size_t)s * H))[lane];
        acc.x += v.x; acc.y += v.y; acc.z += v.z; acc.w += v.w;
    }
    float iv = 1.f / fmaxf((float)(e - b), 1.f);
    acc.x *= iv; acc.y *= iv; acc.z *= iv; acc.w *= iv;
    ((float4*)(g_agg + (size_t)n * H))[lane] = acc;
}

// ================= layers 0/1 GEMM (256 thr, 8 warps; prefetch + convert) ======
#define T64 ((NDV + 63) >> 6)
#define MM_BHI 0
#define MM_BLO 65536
#define MM_AHI 131072
#define MM_ALO 163840
#define MM_STAT 196608
#define MM_TOT (196608 + 1024)

__global__ __launch_bounds__(256, 1)
void k_gemm01mma(const float* __restrict__ Aext, int use_gh,
                 const float* __restrict__ Wself, const float* __restrict__ Wneigh) {
    extern __shared__ char smem[];
    uint32_t sb = s2u(smem);
    float* ssum = (float*)(smem + MM_STAT);
    float* ssq  = ssum + H;
    const int tid = threadIdx.x, lane = tid & 31, wid = tid >> 5;
    const float* A = use_gh ? (const float*)g_h : Aext;

    for (int it = 0; it < 16; ++it) {
        int idx = tid + (it << 8);
        int k = idx >> 4, nc = idx & 15, n0 = nc << 3;
        const float* wsrc = (k < 128) ? (Wself + k * H + n0) : (Wneigh + (k - 128) * H + n0);
        float4 v0 = *(const float4*)(wsrc);
        float4 v1 = *(const float4*)(wsrc + 4);
        uint32_t off = (uint32_t)k * 256 + (uint32_t)((nc ^ (k & 7)) << 4);
        *(uint4*)(smem + MM_BHI + off) = make_uint4(
            pkbf(v0.x, v0.y), pkbf(v0.z, v0.w), pkbf(v1.x, v1.y), pkbf(v1.z, v1.w));
        *(uint4*)(smem + MM_BLO + off) = make_uint4(
            pkbf(bflo(v0.x), bflo(v0.y)), pkbf(bflo(v0.z), bflo(v0.w)),
            pkbf(bflo(v1.x), bflo(v1.y)), pkbf(bflo(v1.z), bflo(v1.w)));
    }
    if (tid < H) { ssum[tid] = 0.f; ssq[tid] = 0.f; }
    __syncthreads();

    const int wm = wid & 1, wn = wid >> 1;
    const int rbase = wm << 5, nbase = wn << 5;
    const int l7 = lane & 7, kp = lane >> 4, l15 = lane & 15;
    const int g = lane >> 2, tq = lane & 3;
    const uint32_t aRowHi = sb + MM_AHI + (uint32_t)(rbase + l15) * 512;
    const uint32_t aRowLo = aRowHi + (MM_ALO - MM_AHI);
    const int nb0 = (nbase >> 3) + kp;
    const uint32_t bch0 = (uint32_t)((nb0 ^ l7) << 4);
    const uint32_t bch1 = (uint32_t)(((nb0 + 2) ^ l7) << 4);
    const uint32_t bHiBase = sb + MM_BHI + (uint32_t)l15 * 256;
    const uint32_t bLoBase = sb + MM_BLO + (uint32_t)l15 * 256;

    const int srow = tid >> 2, skq = (tid & 3) << 6;
    const bool selfHalf = skq < 128;
    float csum[8], csq[8];
    #pragma unroll
    for (int i = 0; i < 8; ++i) { csum[i] = 0.f; csq[i] = 0.f; }

    float4 pre[16];
    auto do_prefetch = [&](int t0p) {
        int rowg = t0p + srow;
        bool valid = rowg < NDV;
        const float* srcp = selfHalf ? (A + (size_t)rowg * H + skq)
                                     : (g_agg + (size_t)rowg * H + (skq - 128));
        #pragma unroll
        for (int j = 0; j < 16; ++j)
            pre[j] = valid ? *(const float4*)(srcp + (j << 2))
                           : make_float4(0.f, 0.f, 0.f, 0.f);
    };

    do_prefetch(blockIdx.x << 6);

    for (int t = blockIdx.x; t < T64; t += gridDim.x) {
        int t0 = t << 6;
        __syncthreads();
        {
            uint32_t rowoff = (uint32_t)srow * 512;
            int rs = srow & 7;
            #pragma unroll
            for (int j = 0; j < 16; ++j) {
                float4 v = pre[j];
                int k = skq + (j << 2);
                uint32_t off = rowoff + (uint32_t)(((k >> 3) ^ rs) << 4) + (uint32_t)((k & 7) << 1);
                *(uint2*)(smem + MM_AHI + off) = make_uint2(pkbf(v.x, v.y), pkbf(v.z, v.w));
                *(uint2*)(smem + MM_ALO + off) = make_uint2(pkbf(bflo(v.x), bflo(v.y)),
                                                            pkbf(bflo(v.z), bflo(v.w)));
            }
        }
        __syncthreads();
        int tn = t + gridDim.x;
        if (tn < T64) do_prefetch(tn << 6);

        float d[2][4][4];
        #pragma unroll
        for (int m = 0; m < 2; ++m)
            #pragma unroll
            for (int nb = 0; nb < 4; ++nb)
                #pragma unroll
                for (int e = 0; e < 4; ++e) d[m][nb][e] = 0.f;

        #pragma unroll 4
        for (int ks = 0; ks < 16; ++ks) {
            uint32_t ach = (uint32_t)((((ks << 1) + kp) ^ l7) << 4);
            uint32_t ahi0[4], ahi1[4], alo0[4], alo1[4];
            ldmA(ahi0, aRowHi + ach);
            ldmA(ahi1, aRowHi + 8192 + ach);
            ldmA(alo0, aRowLo + ach);
            ldmA(alo1, aRowLo + 8192 + ach);
            uint32_t bks = (uint32_t)ks << 12;
            uint32_t bh0[4], bh1[4], bl0[4], bl1[4];
            ldmBT(bh0, bHiBase + bks + bch0);
            ldmBT(bh1, bHiBase + bks + bch1);
            ldmBT(bl0, bLoBase + bks + bch0);
            ldmBT(bl1, bLoBase + bks + bch1);
            mmabf(d[0][0], ahi0, bh0); mmabf(d[0][1], ahi0, bh0 + 2);
            mmabf(d[0][2], ahi0, bh1); mmabf(d[0][3], ahi0, bh1 + 2);
            mmabf(d[1][0], ahi1, bh0); mmabf(d[1][1], ahi1, bh0 + 2);
            mmabf(d[1][2], ahi1, bh1); mmabf(d[1][3], ahi1, bh1 + 2);
            mmabf(d[0][0], ahi0, bl0); mmabf(d[0][1], ahi0, bl0 + 2);
            mmabf(d[0][2], ahi0, bl1); mmabf(d[0][3], ahi0, bl1 + 2);
            mmabf(d[1][0], ahi1, bl0); mmabf(d[1][1], ahi1, bl0 + 2);
            mmabf(d[1][2], ahi1, bl1); mmabf(d[1][3], ahi1, bl1 + 2);
            mmabf(d[0][0], alo0, bh0); mmabf(d[0][1], alo0, bh0 + 2);
            mmabf(d[0][2], alo0, bh1); mmabf(d[0][3], alo0, bh1 + 2);
            mmabf(d[1][0], alo1, bh0); mmabf(d[1][1], alo1, bh0 + 2);
            mmabf(d[1][2], alo1, bh1); mmabf(d[1][3], alo1, bh1 + 2);
        }

        #pragma unroll
        for (int m = 0; m < 2; ++m) {
            int row0 = t0 + rbase + (m << 4) + g;
            int row1 = row0 + 8;
            if (row0 < NDV) {
                float* o = g_out + (size_t)row0 * H + nbase + (tq << 1);
                #pragma unroll
                for (int nb = 0; nb < 4; ++nb) {
                    *(float2*)(o + (nb << 3)) = make_float2(d[m][nb][0], d[m][nb][1]);
                    csum[nb * 2 + 0] += d[m][nb][0]; csq[nb * 2 + 0] += d[m][nb][0] * d[m][nb][0];
                    csum[nb * 2 + 1] += d[m][nb][1]; csq[nb * 2 + 1] += d[m][nb][1] * d[m][nb][1];
                }
            }
            if (row1 < NDV) {
                float* o = g_out + (size_t)row1 * H + nbase + (tq << 1);
                #pragma unroll
                for (int nb = 0; nb < 4; ++nb) {
                    *(float2*)(o + (nb << 3)) = make_float2(d[m][nb][2], d[m][nb][3]);
                    csum[nb * 2 + 0] += d[m][nb][2]; csq[nb * 2 + 0] += d[m][nb][2] * d[m][nb][2];
                    csum[nb * 2 + 1] += d[m][nb][3]; csq[nb * 2 + 1] += d[m][nb][3] * d[m][nb][3];
                }
            }
        }
    }

    #pragma unroll
    for (int nb = 0; nb < 4; ++nb)
        #pragma unroll
        for (int j = 0; j < 2; ++j) {
            int col = nbase + (tq << 1) + (nb << 3) + j;
            atomicAdd(&ssum[col], csum[nb * 2 + j]);
            atomicAdd(&ssq[col],  csq[nb * 2 + j]);
        }
    __syncthreads();
    if (tid < H) {
        atomicAdd(&g_sum[tid], ssum[tid]);
        atomicAdd(&g_sq[tid],  ssq[tid]);
    }
}

// consumes stats AND re-zeroes them (replay-invariant)
__global__ void k_bnfin(const float* __restrict__ gamma, const float* __restrict__ beta) {
    int c = threadIdx.x;
    float mean = g_sum[c] * (1.f / NDV);
    float var  = g_sq[c]  * (1.f / NDV) - mean * mean;
    float sc = gamma[c] * rsqrtf(var + 1e-5f);
    g_scale[c] = sc;
    g_shift[c] = beta[c] - mean * sc;
    g_sum[c] = 0.f;
    g_sq[c]  = 0.f;
}

// once-per-node BN+ReLU: g_h = relu(g_out*scale+shift)
__global__ void k_apply() {
    int i = blockIdx.x * blockDim.x + threadIdx.x;
    if (i >= NDV * 32) return;
    int c4 = i & 31;
    float4 v  = ((const float4*)g_out)[i];
    float4 sc = ((const float4*)g_scale)[c4];
    float4 sh = ((const float4*)g_shift)[c4];
    v.x = fmaxf(fmaf(v.x, sc.x, sh.x), 0.f);
    v.y = fmaxf(fmaf(v.y, sc.y, sh.y), 0.f);
    v.z = fmaxf(fmaf(v.z, sc.z, sh.z), 0.f);
    v.w = fmaxf(fmaf(v.w, sc.w, sh.w), 0.f);
    ((float4*)g_h)[i] = v;
}

// ================= layer 2 GEMM via mma.sync bf16 (3-term split) ===============
#define M2_BHI 0
#define M2_BLO 32768
#define M2_AHI 65536
#define M2_ALO 81920
#define M2_TOT 98304

__global__ __launch_bounds__(256, 1)
void k_gemm2mma(const float* __restrict__ Wself, const float* __restrict__ Wneigh,
                const float* __restrict__ bias, float* __restrict__ out) {
    extern __shared__ char smem[];
    uint32_t sb = s2u(smem);
    const int tid = threadIdx.x, lane = tid & 31, wid = tid >> 5;

    for (int it = 0; it < 8; ++it) {
        int idx = tid + (it << 8);
        int k = idx >> 4, nc = idx & 15, n0 = nc << 3;
        float4 v0 = make_float4(0.f, 0.f, 0.f, 0.f), v1 = v0;
        if (n0 < 40) {
            const float* w = Wself + k * OD + n0;
            v0 = *(const float4*)(w); v1 = *(const float4*)(w + 4);
        } else if (n0 < 80) {
            const float* w = Wneigh + k * OD + (n0 - 40);
            v0 = *(const float4*)(w); v1 = *(const float4*)(w + 4);
        }
        uint32_t off = (uint32_t)k * 256 + (uint32_t)((nc ^ (k & 7)) << 4);
        *(uint4*)(smem + M2_BHI + off) = make_uint4(
            pkbf(v0.x, v0.y), pkbf(v0.z, v0.w), pkbf(v1.x, v1.y), pkbf(v1.z, v1.w));
        *(uint4*)(smem + M2_BLO + off) = make_uint4(
            pkbf(bflo(v0.x), bflo(v0.y)), pkbf(bflo(v0.z), bflo(v0.w)),
            pkbf(bflo(v1.x), bflo(v1.y)), pkbf(bflo(v1.z), bflo(v1.w)));
    }
    __syncthreads();

    const int wm = wid & 1, wn = wid >> 1;
    const int rbase = wm << 5, nbase = wn << 5;
    const int l7 = lane & 7, kp = lane >> 4, l15 = lane & 15;
    const int g = lane >> 2, tq = lane & 3;
    const uint32_t aRowHi = sb + M2_AHI + (uint32_t)(rbase + l15) * 256;
    const uint32_t aRowLo = aRowHi + (M2_ALO - M2_AHI);
    const int nb0 = (nbase >> 3) + kp;
    const uint32_t bch0 = (uint32_t)((nb0 ^ l7) << 4);
    const uint32_t bch1 = (uint32_t)(((nb0 + 2) ^ l7) << 4);
    const uint32_t bHiBase = sb + M2_BHI + (uint32_t)l15 * 256;
    const uint32_t bLoBase = sb + M2_BLO + (uint32_t)l15 * 256;

    const int srow = tid >> 2, skq = (tid & 3) << 5;

    for (int t = blockIdx.x; t < T64; t += gridDim.x) {
        int t0 = t << 6;
        __syncthreads();
        {
            int rowg = t0 + srow;
            bool valid = rowg < NDV;
            const float* srcp = (const float*)g_h + (size_t)rowg * H + skq;
            uint32_t rowoff = (uint32_t)srow * 256;
            int rs = srow & 7;
            #pragma unroll
            for (int j = 0; j < 8; ++j) {
                float4 v = valid ? *(const float4*)(srcp + (j << 2))
                                 : make_float4(0.f, 0.f, 0.f, 0.f);
                int k = skq + (j << 2);
                uint32_t off = rowoff + (uint32_t)(((k >> 3) ^ rs) << 4) + (uint32_t)((k & 7) << 1);
                *(uint2*)(smem + M2_AHI + off) = make_uint2(pkbf(v.x, v.y), pkbf(v.z, v.w));
                *(uint2*)(smem + M2_ALO + off) = make_uint2(pkbf(bflo(v.x), bflo(v.y)),
                                                            pkbf(bflo(v.z), bflo(v.w)));
            }
        }
        __syncthreads();

        float d[2][4][4];
        #pragma unroll
        for (int m = 0; m < 2; ++m)
            #pragma unroll
            for (int nb = 0; nb < 4; ++nb)
                #pragma unroll
                for (int e = 0; e < 4; ++e) d[m][nb][e] = 0.f;

        #pragma unroll 4
        for (int ks = 0; ks < 8; ++ks) {
            uint32_t ach = (uint32_t)((((ks << 1) + kp) ^ l7) << 4);
            uint32_t ahi0[4], ahi1[4], alo0[4], alo1[4];
            ldmA(ahi0, aRowHi + ach);
            ldmA(ahi1, aRowHi + 4096 + ach);
            ldmA(alo0, aRowLo + ach);
            ldmA(alo1, aRowLo + 4096 + ach);
            uint32_t bks = (uint32_t)ks << 12;
            uint32_t bh0[4], bh1[4], bl0[4], bl1[4];
            ldmBT(bh0, bHiBase + bks + bch0);
            ldmBT(bh1, bHiBase + bks + bch1);
            ldmBT(bl0, bLoBase + bks + bch0);
            ldmBT(bl1, bLoBase + bks + bch1);
            mmabf(d[0][0], ahi0, bh0); mmabf(d[0][1], ahi0, bh0 + 2);
            mmabf(d[0][2], ahi0, bh1); mmabf(d[0][3], ahi0, bh1 + 2);
            mmabf(d[1][0], ahi1, bh0); mmabf(d[1][1], ahi1, bh0 + 2);
            mmabf(d[1][2], ahi1, bh1); mmabf(d[1][3], ahi1, bh1 + 2);
            mmabf(d[0][0], ahi0, bl0); mmabf(d[0][1], ahi0, bl0 + 2);
            mmabf(d[0][2], ahi0, bl1); mmabf(d[0][3], ahi0, bl1 + 2);
            mmabf(d[1][0], ahi1, bl0); mmabf(d[1][1], ahi1, bl0 + 2);
            mmabf(d[1][2], ahi1, bl1); mmabf(d[1][3], ahi1, bl1 + 2);
            mmabf(d[0][0], alo0, bh0); mmabf(d[0][1], alo0, bh0 + 2);
            mmabf(d[0][2], alo0, bh1); mmabf(d[0][3], alo0, bh1 + 2);
            mmabf(d[1][0], alo1, bh0); mmabf(d[1][1], alo1, bh0 + 2);
            mmabf(d[1][2], alo1, bh1); mmabf(d[1][3], alo1, bh1 + 2);
        }

        #pragma unroll
        for (int m = 0; m < 2; ++m) {
            int row0 = t0 + rbase + (m << 4) + g;
            int row1 = row0 + 8;
            #pragma unroll
            for (int nb = 0; nb < 4; ++nb) {
                int col = nbase + (tq << 1) + (nb << 3);
                #pragma unroll
                for (int j = 0; j < 2; ++j) {
                    int c = col + j;
                    if (c < 40) {
                        if (row0 < NDV) out[(size_t)row0 * OD + c] = d[m][nb][j] + bias[c];
                        if (row1 < NDV) out[(size_t)row1 * OD + c] = d[m][nb][j + 2] + bias[c];
                    } else if (c < 80) {
                        if (row0 < NDV) g_p[(size_t)row0 * OD + c - 40] = d[m][nb][j];
                        if (row1 < NDV) g_p[(size_t)row1 * OD + c - 40] = d[m][nb][j + 2];
                    }
                }
            }
        }
    }
}

// CSR layer-2 neighbor mean: 10 threads per node, 4-edge-batched p reads
__global__ void k_edge2csr(float* __restrict__ out) {
    int idx = blockIdx.x * blockDim.x + threadIdx.x;
    if (idx >= NDV * 10) return;
    int n = idx / 10, c4 = idx - n * 10;
    int b = g_rowstart[n], e = g_rowstart[n + 1];
    float4 acc = make_float4(0.f, 0.f, 0.f, 0.f);
    int i = b;
    for (; i + 4 <= e; i += 4) {
        int s0 = g_csr_src[i], s1 = g_csr_src[i + 1];
        int s2 = g_csr_src[i + 2], s3 = g_csr_src[i + 3];
        float4 v0 = *(const float4*)(g_p + (size_t)s0 * OD + c4 * 4);
        float4 v1 = *(const float4*)(g_p + (size_t)s1 * OD + c4 * 4);
        float4 v2 = *(const float4*)(g_p + (size_t)s2 * OD + c4 * 4);
        float4 v3 = *(const float4*)(g_p + (size_t)s3 * OD + c4 * 4);
        acc.x += (v0.x + v1.x) + (v2.x + v3.x);
        acc.y += (v0.y + v1.y) + (v2.y + v3.y);
        acc.z += (v0.z + v1.z) + (v2.z + v3.z);
        acc.w += (v0.w + v1.w) + (v2.w + v3.w);
    }
    for (; i < e; ++i) {
        int s = g_csr_src[i];
        float4 v = *(const float4*)(g_p + (size_t)s * OD + c4 * 4);
        acc.x += v.x; acc.y += v.y; acc.z += v.z; acc.w += v.w;
    }
    float iv = 1.f / fmaxf((float)(e - b), 1.f);
    float* o = out + (size_t)n * OD + c4 * 4;
    float4 cur = *(float4*)o;
    cur.x += acc.x * iv; cur.y += acc.y * iv;
    cur.z += acc.z * iv; cur.w += acc.w * iv;
    *(float4*)o = cur;
}

// ---------------- host launcher ------------------------------------------------
extern "C" void kernel_launch(void* const* d_in, const int* in_sizes, int n_in,
                              void* d_out, int out_size) {
    const float* feat = (const float*)d_in[0];
    const int*   src  = (const int*)d_in[1];
    const int*   dst  = (const int*)d_in[2];
    const float* Ws0 = (const float*)d_in[3];
    const float* Wn0 = (const float*)d_in[4];
    const float* ga0 = (const float*)d_in[5];
    const float* be0 = (const float*)d_in[6];
    const float* Ws1 = (const float*)d_in[7];
    const float* Wn1 = (const float*)d_in[8];
    const float* ga1 = (const float*)d_in[9];
    const float* be1 = (const float*)d_in[10];
    const float* Ws2 = (const float*)d_in[11];
    const float* Wn2 = (const float*)d_in[12];
    const float* b2  = (const float*)d_in[13];
    float* out = (float*)d_out;

    cudaFuncSetAttribute(k_gemm01mma, cudaFuncAttributeMaxDynamicSharedMemorySize, MM_TOT);
    cudaFuncSetAttribute(k_gemm2mma,  cudaFuncAttributeMaxDynamicSharedMemorySize, M2_TOT);

    const int TB = 256;
    // CSR build (scan2 merged into scan3)
    k_zdegi<<<(NDV + TB - 1) / TB, TB>>>();
    k_degi<<<(NE + TB - 1) / TB, TB>>>(dst);
    k_scan1<<<SCB, 1024>>>();
    k_scan3<<<SCB, 1024>>>();
    k_scatter<<<(NE + TB - 1) / TB, TB>>>(src, dst);

    // ---- layer 0 ----
    k_aggcsr<<<(NDV * 32 + TB - 1) / TB, TB>>>(feat, 0);
    k_gemm01mma<<<148, 256, MM_TOT>>>(feat, 0, Ws0, Wn0);
    k_bnfin<<<1, 128>>>(ga0, be0);
    k_apply<<<(NDV * 32 + TB - 1) / TB, TB>>>();

    // ---- layer 1 ----
    k_aggcsr<<<(NDV * 32 + TB - 1) / TB, TB>>>(nullptr, 1);
    k_gemm01mma<<<148, 256, MM_TOT>>>(nullptr, 1, Ws1, Wn1);
    k_bnfin<<<1, 128>>>(ga1, be1);
    k_apply<<<(NDV * 32 + TB - 1) / TB, TB>>>();

    // ---- layer 2 ----
    k_gemm2mma<<<148, 256, M2_TOT>>>(Ws2, Wn2, b2, out);
    k_edge2csr<<<(NDV * 10 + TB - 1) / TB, TB>>>(out);

    (void)in_sizes; (void)n_in; (void)out_size;
}

// round 17
// speedup vs baseline: 1.1336x; 1.0481x over previous
#include <cuda_runtime.h>
#include <cuda_bf16.h>
#include <cstdint>

#define NDV 100000
#define NE  800000
#define H   128
#define OD  40
#define SCB 98        // scan blocks of 1024

// ---------------- device scratch (static globals: allocation-free) -------------
__device__ float g_agg[(size_t)NDV * H];
__device__ float g_out[(size_t)NDV * H];
__device__ float g_h  [(size_t)NDV * H];
__device__ float g_p  [(size_t)NDV * OD];
__device__ int   g_degi[NDV];
__device__ int   g_rowstart[NDV + 1];
__device__ int   g_cursor[NDV];
__device__ int   g_csr_src[NE];
__device__ int   g_bsum[SCB];
__device__ float g_sum[H];      // zero at load; k_bnfin re-zeroes after consuming
__device__ float g_sq [H];
__device__ float g_scale[H];
__device__ float g_shift[H];

// ---------------- helpers ------------------------------------------------------
__device__ __forceinline__ uint32_t s2u(const void* p) {
    uint32_t a;
    asm("{ .reg .u64 t; cvta.to.shared.u64 t, %1; cvt.u32.u64 %0, t; }" : "=r"(a) : "l"(p));
    return a;
}
__device__ __forceinline__ uint32_t pkbf(float a, float b) {
    __nv_bfloat162 t = __halves2bfloat162(__float2bfloat16(a), __float2bfloat16(b));
    return *(uint32_t*)&t;
}
__device__ __forceinline__ float bflo(float x) {
    __nv_bfloat16 h = __float2bfloat16(x);
    return x - __bfloat162float(h);
}
__device__ __forceinline__ void ldmA(uint32_t* r, uint32_t a) {
    asm volatile("ldmatrix.sync.aligned.m8n8.x4.shared.b16 {%0,%1,%2,%3},[%4];"
                 : "=r"(r[0]), "=r"(r[1]), "=r"(r[2]), "=r"(r[3]) : "r"(a));
}
__device__ __forceinline__ void ldmBT(uint32_t* r, uint32_t a) {
    asm volatile("ldmatrix.sync.aligned.m8n8.x4.trans.shared.b16 {%0,%1,%2,%3},[%4];"
                 : "=r"(r[0]), "=r"(r[1]), "=r"(r[2]), "=r"(r[3]) : "r"(a));
}
__device__ __forceinline__ void mmabf(float* d, const uint32_t* a, const uint32_t* b) {
    asm volatile("mma.sync.aligned.m16n8k16.row.col.f32.bf16.bf16.f32 "
                 "{%0,%1,%2,%3},{%4,%5,%6,%7},{%8,%9},{%0,%1,%2,%3};"
                 : "+f"(d[0]), "+f"(d[1]), "+f"(d[2]), "+f"(d[3])
                 : "r"(a[0]), "r"(a[1]), "r"(a[2]), "r"(a[3]), "r"(b[0]), "r"(b[1]));
}
__device__ __forceinline__ float4 bn4(float4 v, float4 sc, float4 sh) {
    v.x = fmaxf(fmaf(v.x, sc.x, sh.x), 0.f);
    v.y = fmaxf(fmaf(v.y, sc.y, sh.y), 0.f);
    v.z = fmaxf(fmaf(v.z, sc.z, sh.z), 0.f);
    v.w = fmaxf(fmaf(v.w, sc.w, sh.w), 0.f);
    return v;
}

// ---------------- CSR build ----------------------------------------------------
__global__ void k_zdegi() {
    int i = blockIdx.x * blockDim.x + threadIdx.x;
    if (i < NDV) g_degi[i] = 0;
}
__global__ void k_degi(const int* __restrict__ dst) {
    int e = blockIdx.x * blockDim.x + threadIdx.x;
    if (e < NE) atomicAdd(&g_degi[dst[e]], 1);
}
__global__ __launch_bounds__(1024) void k_scan1() {
    __shared__ int sh[32];
    int t = threadIdx.x, i = blockIdx.x * 1024 + t;
    int v = (i < NDV) ? g_degi[i] : 0;
    #pragma unroll
    for (int o = 16; o > 0; o >>= 1) v += __shfl_down_sync(0xffffffffu, v, o);
    if ((t & 31) == 0) sh[t >> 5] = v;
    __syncthreads();
    if (t < 32) {
        int u = sh[t];
        #pragma unroll
        for (int o = 16; o > 0; o >>= 1) u += __shfl_down_sync(0xffffffffu, u, o);
        if (t == 0) g_bsum[blockIdx.x] = u;
    }
}
// block-local exclusive scan; block offset computed in-kernel (merged scan2)
__global__ __launch_bounds__(1024) void k_scan3() {
    __shared__ int wsum[32];
    __shared__ int boffs;
    int t = threadIdx.x, lane = t & 31, w = t >> 5;
    int i = blockIdx.x * 1024 + t;
    int v = (i < NDV) ? g_degi[i] : 0;
    int s = v;
    #pragma unroll
    for (int o = 1; o < 32; o <<= 1) {
        int u = __shfl_up_sync(0xffffffffu, s, o);
        if (lane >= o) s += u;
    }
    if (lane == 31) wsum[w] = s;
    if (w == 1) {   // warp 1 reduces bsum[0..blockIdx.x)
        int acc = 0;
        for (int j = lane; j < (int)blockIdx.x; j += 32) acc += g_bsum[j];
        #pragma unroll
        for (int o = 16; o > 0; o >>= 1) acc += __shfl_down_sync(0xffffffffu, acc, o);
        if (lane == 0) boffs = acc;
    }
    __syncthreads();
    if (t < 32) {
        int u = wsum[t];
        #pragma unroll
        for (int o = 1; o < 32; o <<= 1) {
            int x = __shfl_up_sync(0xffffffffu, u, o);
            if (t >= o) u += x;
        }
        wsum[t] = u;
    }
    __syncthreads();
    int excl = s - v + (w > 0 ? wsum[w - 1] : 0) + boffs;
    if (i < NDV) { g_rowstart[i] = excl; g_cursor[i] = excl; }
    if (i == NDV - 1) g_rowstart[NDV] = excl + v;
}
__global__ void k_scatter(const int* __restrict__ src, const int* __restrict__ dst) {
    int e = blockIdx.x * blockDim.x + threadIdx.x;
    if (e >= NE) return;
    int pos = atomicAdd(&g_cursor[dst[e]], 1);
    g_csr_src[pos] = src[e];
}

// ---- CSR mean-aggregation: warp per node, 4-edge-batched gathers (MLP=4) ------
__global__ void k_aggcsr(const float* __restrict__ hext, int use_gh) {
    int idx = blockIdx.x * blockDim.x + threadIdx.x;
    int n = idx >> 5, lane = idx & 31;
    if (n >= NDV) return;
    const float* h = use_gh ? (const float*)g_h : hext;
    int b = g_rowstart[n], e = g_rowstart[n + 1];
    float4 acc = make_float4(0.f, 0.f, 0.f, 0.f);
    int i = b;
    for (; i + 4 <= e; i += 4) {
        int s0 = g_csr_src[i], s1 = g_csr_src[i + 1];
        int s2 = g_csr_src[i + 2], s3 = g_csr_src[i + 3];
        float4 v0 = ((const float4*)(h + (size_t)s0 * H))[lane];
        float4 v1 = ((const float4*)(h + (size_t)s1 * H))[lane];
        float4 v2 = ((const float4*)(h + (size_t)s2 * H))[lane];
        float4 v3 = ((const float4*)(h + (size_t)s3 * H))[lane];
        acc.x += (v0.x + v1.x) + (v2.x + v3.x);
        acc.y += (v0.y + v1.y) + (v2.y + v3.y);
        acc.z += (v0.z + v1.z) + (v2.z + v3.z);
        acc.w += (v0.w + v1.w) + (v2.w + v3.w);
    }
    for (; i < e; ++i) {
        int s = g_csr_src[i];
        float4 v = ((const float4*)(h + (size_t)s * H))[lane];
        acc.x += v.x; acc.y += v.y; acc.z += v.z; acc.w += v.w;
    }
    float iv = 1.f / fmaxf((float)(e - b), 1.f);
    acc.x *= iv; acc.y *= iv; acc.z *= iv; acc.w *= iv;
    ((float4*)(g_agg + (size_t)n * H))[lane] = acc;
}

// ================= layers 0/1 GEMM (256 thr, 8 warps; prefetch + convert) ======
#define T64 ((NDV + 63) >> 6)
#define MM_BHI 0
#define MM_BLO 65536
#define MM_AHI 131072
#define MM_ALO 163840
#define MM_STAT 196608
#define MM_TOT (196608 + 1024)

__global__ __launch_bounds__(256, 1)
void k_gemm01mma(const float* __restrict__ Aext, int use_gh,
                 const float* __restrict__ Wself, const float* __restrict__ Wneigh) {
    extern __shared__ char smem[];
    uint32_t sb = s2u(smem);
    float* ssum = (float*)(smem + MM_STAT);
    float* ssq  = ssum + H;
    const int tid = threadIdx.x, lane = tid & 31, wid = tid >> 5;
    const float* A = use_gh ? (const float*)g_h : Aext;

    for (int it = 0; it < 16; ++it) {
        int idx = tid + (it << 8);
        int k = idx >> 4, nc = idx & 15, n0 = nc << 3;
        const float* wsrc = (k < 128) ? (Wself + k * H + n0) : (Wneigh + (k - 128) * H + n0);
        float4 v0 = *(const float4*)(wsrc);
        float4 v1 = *(const float4*)(wsrc + 4);
        uint32_t off = (uint32_t)k * 256 + (uint32_t)((nc ^ (k & 7)) << 4);
        *(uint4*)(smem + MM_BHI + off) = make_uint4(
            pkbf(v0.x, v0.y), pkbf(v0.z, v0.w), pkbf(v1.x, v1.y), pkbf(v1.z, v1.w));
        *(uint4*)(smem + MM_BLO + off) = make_uint4(
            pkbf(bflo(v0.x), bflo(v0.y)), pkbf(bflo(v0.z), bflo(v0.w)),
            pkbf(bflo(v1.x), bflo(v1.y)), pkbf(bflo(v1.z), bflo(v1.w)));
    }
    if (tid < H) { ssum[tid] = 0.f; ssq[tid] = 0.f; }
    __syncthreads();

    const int wm = wid & 1, wn = wid >> 1;
    const int rbase = wm << 5, nbase = wn << 5;
    const int l7 = lane & 7, kp = lane >> 4, l15 = lane & 15;
    const int g = lane >> 2, tq = lane & 3;
    const uint32_t aRowHi = sb + MM_AHI + (uint32_t)(rbase + l15) * 512;
    const uint32_t aRowLo = aRowHi + (MM_ALO - MM_AHI);
    const int nb0 = (nbase >> 3) + kp;
    const uint32_t bch0 = (uint32_t)((nb0 ^ l7) << 4);
    const uint32_t bch1 = (uint32_t)(((nb0 + 2) ^ l7) << 4);
    const uint32_t bHiBase = sb + MM_BHI + (uint32_t)l15 * 256;
    const uint32_t bLoBase = sb + MM_BLO + (uint32_t)l15 * 256;

    const int srow = tid >> 2, skq = (tid & 3) << 6;
    const bool selfHalf = skq < 128;
    float csum[8], csq[8];
    #pragma unroll
    for (int i = 0; i < 8; ++i) { csum[i] = 0.f; csq[i] = 0.f; }

    float4 pre[16];
    auto do_prefetch = [&](int t0p) {
        int rowg = t0p + srow;
        bool valid = rowg < NDV;
        const float* srcp = selfHalf ? (A + (size_t)rowg * H + skq)
                                     : (g_agg + (size_t)rowg * H + (skq - 128));
        #pragma unroll
        for (int j = 0; j < 16; ++j)
            pre[j] = valid ? *(const float4*)(srcp + (j << 2))
                           : make_float4(0.f, 0.f, 0.f, 0.f);
    };

    do_prefetch(blockIdx.x << 6);

    for (int t = blockIdx.x; t < T64; t += gridDim.x) {
        int t0 = t << 6;
        __syncthreads();
        {
            uint32_t rowoff = (uint32_t)srow * 512;
            int rs = srow & 7;
            #pragma unroll
            for (int j = 0; j < 16; ++j) {
                float4 v = pre[j];
                int k = skq + (j << 2);
                uint32_t off = rowoff + (uint32_t)(((k >> 3) ^ rs) << 4) + (uint32_t)((k & 7) << 1);
                *(uint2*)(smem + MM_AHI + off) = make_uint2(pkbf(v.x, v.y), pkbf(v.z, v.w));
                *(uint2*)(smem + MM_ALO + off) = make_uint2(pkbf(bflo(v.x), bflo(v.y)),
                                                            pkbf(bflo(v.z), bflo(v.w)));
            }
        }
        __syncthreads();
        int tn = t + gridDim.x;
        if (tn < T64) do_prefetch(tn << 6);

        float d[2][4][4];
        #pragma unroll
        for (int m = 0; m < 2; ++m)
            #pragma unroll
            for (int nb = 0; nb < 4; ++nb)
                #pragma unroll
                for (int e = 0; e < 4; ++e) d[m][nb][e] = 0.f;

        #pragma unroll 4
        for (int ks = 0; ks < 16; ++ks) {
            uint32_t ach = (uint32_t)((((ks << 1) + kp) ^ l7) << 4);
            uint32_t ahi0[4], ahi1[4], alo0[4], alo1[4];
            ldmA(ahi0, aRowHi + ach);
            ldmA(ahi1, aRowHi + 8192 + ach);
            ldmA(alo0, aRowLo + ach);
            ldmA(alo1, aRowLo + 8192 + ach);
            uint32_t bks = (uint32_t)ks << 12;
            uint32_t bh0[4], bh1[4], bl0[4], bl1[4];
            ldmBT(bh0, bHiBase + bks + bch0);
            ldmBT(bh1, bHiBase + bks + bch1);
            ldmBT(bl0, bLoBase + bks + bch0);
            ldmBT(bl1, bLoBase + bks + bch1);
            mmabf(d[0][0], ahi0, bh0); mmabf(d[0][1], ahi0, bh0 + 2);
            mmabf(d[0][2], ahi0, bh1); mmabf(d[0][3], ahi0, bh1 + 2);
            mmabf(d[1][0], ahi1, bh0); mmabf(d[1][1], ahi1, bh0 + 2);
            mmabf(d[1][2], ahi1, bh1); mmabf(d[1][3], ahi1, bh1 + 2);
            mmabf(d[0][0], ahi0, bl0); mmabf(d[0][1], ahi0, bl0 + 2);
            mmabf(d[0][2], ahi0, bl1); mmabf(d[0][3], ahi0, bl1 + 2);
            mmabf(d[1][0], ahi1, bl0); mmabf(d[1][1], ahi1, bl0 + 2);
            mmabf(d[1][2], ahi1, bl1); mmabf(d[1][3], ahi1, bl1 + 2);
            mmabf(d[0][0], alo0, bh0); mmabf(d[0][1], alo0, bh0 + 2);
            mmabf(d[0][2], alo0, bh1); mmabf(d[0][3], alo0, bh1 + 2);
            mmabf(d[1][0], alo1, bh0); mmabf(d[1][1], alo1, bh0 + 2);
            mmabf(d[1][2], alo1, bh1); mmabf(d[1][3], alo1, bh1 + 2);
        }

        #pragma unroll
        for (int m = 0; m < 2; ++m) {
            int row0 = t0 + rbase + (m << 4) + g;
            int row1 = row0 + 8;
            if (row0 < NDV) {
                float* o = g_out + (size_t)row0 * H + nbase + (tq << 1);
                #pragma unroll
                for (int nb = 0; nb < 4; ++nb) {
                    *(float2*)(o + (nb << 3)) = make_float2(d[m][nb][0], d[m][nb][1]);
                    csum[nb * 2 + 0] += d[m][nb][0]; csq[nb * 2 + 0] += d[m][nb][0] * d[m][nb][0];
                    csum[nb * 2 + 1] += d[m][nb][1]; csq[nb * 2 + 1] += d[m][nb][1] * d[m][nb][1];
                }
            }
            if (row1 < NDV) {
                float* o = g_out + (size_t)row1 * H + nbase + (tq << 1);
                #pragma unroll
                for (int nb = 0; nb < 4; ++nb) {
                    *(float2*)(o + (nb << 3)) = make_float2(d[m][nb][2], d[m][nb][3]);
                    csum[nb * 2 + 0] += d[m][nb][2]; csq[nb * 2 + 0] += d[m][nb][2] * d[m][nb][2];
                    csum[nb * 2 + 1] += d[m][nb][3]; csq[nb * 2 + 1] += d[m][nb][3] * d[m][nb][3];
                }
            }
        }
    }

    #pragma unroll
    for (int nb = 0; nb < 4; ++nb)
        #pragma unroll
        for (int j = 0; j < 2; ++j) {
            int col = nbase + (tq << 1) + (nb << 3) + j;
            atomicAdd(&ssum[col], csum[nb * 2 + j]);
            atomicAdd(&ssq[col],  csq[nb * 2 + j]);
        }
    __syncthreads();
    if (tid < H) {
        atomicAdd(&g_sum[tid], ssum[tid]);
        atomicAdd(&g_sq[tid],  ssq[tid]);
    }
}

// consumes stats AND re-zeroes them (replay-invariant)
__global__ void k_bnfin(const float* __restrict__ gamma, const float* __restrict__ beta) {
    int c = threadIdx.x;
    float mean = g_sum[c] * (1.f / NDV);
    float var  = g_sq[c]  * (1.f / NDV) - mean * mean;
    float sc = gamma[c] * rsqrtf(var + 1e-5f);
    g_scale[c] = sc;
    g_shift[c] = beta[c] - mean * sc;
    g_sum[c] = 0.f;
    g_sq[c]  = 0.f;
}

// once-per-node BN+ReLU (layer 0 only): g_h = relu(g_out*scale+shift)
__global__ void k_apply() {
    int i = blockIdx.x * blockDim.x + threadIdx.x;
    if (i >= NDV * 32) return;
    int c4 = i & 31;
    float4 v  = ((const float4*)g_out)[i];
    float4 sc = ((const float4*)g_scale)[c4];
    float4 sh = ((const float4*)g_shift)[c4];
    ((float4*)g_h)[i] = bn4(v, sc, sh);
}

// ================= layer 2 GEMM: BN1+ReLU fused into staging, prefetched =======
#define M2_BHI 0
#define M2_BLO 32768
#define M2_AHI 65536
#define M2_ALO 81920
#define M2_TOT 98304

__global__ __launch_bounds__(256, 1)
void k_gemm2mma(const float* __restrict__ Wself, const float* __restrict__ Wneigh,
                const float* __restrict__ bias, float* __restrict__ out) {
    extern __shared__ char smem[];
    uint32_t sb = s2u(smem);
    const int tid = threadIdx.x, lane = tid & 31, wid = tid >> 5;

    for (int it = 0; it < 8; ++it) {
        int idx = tid + (it << 8);
        int k = idx >> 4, nc = idx & 15, n0 = nc << 3;
        float4 v0 = make_float4(0.f, 0.f, 0.f, 0.f), v1 = v0;
        if (n0 < 40) {
            const float* w = Wself + k * OD + n0;
            v0 = *(const float4*)(w); v1 = *(const float4*)(w + 4);
        } else if (n0 < 80) {
            const float* w = Wneigh + k * OD + (n0 - 40);
            v0 = *(const float4*)(w); v1 = *(const float4*)(w + 4);
        }
        uint32_t off = (uint32_t)k * 256 + (uint32_t)((nc ^ (k & 7)) << 4);
        *(uint4*)(smem + M2_BHI + off) = make_uint4(
            pkbf(v0.x, v0.y), pkbf(v0.z, v0.w), pkbf(v1.x, v1.y), pkbf(v1.z, v1.w));
        *(uint4*)(smem + M2_BLO + off) = make_uint4(
            pkbf(bflo(v0.x), bflo(v0.y)), pkbf(bflo(v0.z), bflo(v0.w)),
            pkbf(bflo(v1.x), bflo(v1.y)), pkbf(bflo(v1.z), bflo(v1.w)));
    }
    __syncthreads();

    const int wm = wid & 1, wn = wid >> 1;
    const int rbase = wm << 5, nbase = wn << 5;
    const int l7 = lane & 7, kp = lane >> 4, l15 = lane & 15;
    const int g = lane >> 2, tq = lane & 3;
    const uint32_t aRowHi = sb + M2_AHI + (uint32_t)(rbase + l15) * 256;
    const uint32_t aRowLo = aRowHi + (M2_ALO - M2_AHI);
    const int nb0 = (nbase >> 3) + kp;
    const uint32_t bch0 = (uint32_t)((nb0 ^ l7) << 4);
    const uint32_t bch1 = (uint32_t)(((nb0 + 2) ^ l7) << 4);
    const uint32_t bHiBase = sb + M2_BHI + (uint32_t)l15 * 256;
    const uint32_t bLoBase = sb + M2_BLO + (uint32_t)l15 * 256;

    const int srow = tid >> 2, skq = (tid & 3) << 5;
    // per-thread BN constants for its 32-k slice (8 float4)
    float4 scq[8], shq[8];
    #pragma unroll
    for (int j = 0; j < 8; ++j) {
        scq[j] = *(const float4*)(g_scale + skq + (j << 2));
        shq[j] = *(const float4*)(g_shift + skq + (j << 2));
    }

    float4 pre[8];
    auto do_prefetch = [&](int t0p) {
        int rowg = t0p + srow;
        bool valid = rowg < NDV;
        const float* srcp = (const float*)g_out + (size_t)rowg * H + skq;
        #pragma unroll
        for (int j = 0; j < 8; ++j)
            pre[j] = valid ? *(const float4*)(srcp + (j << 2))
                           : make_float4(0.f, 0.f, 0.f, 0.f);
    };

    do_prefetch(blockIdx.x << 6);

    for (int t = blockIdx.x; t < T64; t += gridDim.x) {
        int t0 = t << 6;
        __syncthreads();
        {
            uint32_t rowoff = (uint32_t)srow * 256;
            int rs = srow & 7;
            #pragma unroll
            for (int j = 0; j < 8; ++j) {
                float4 v = bn4(pre[j], scq[j], shq[j]);
                int k = skq + (j << 2);
                uint32_t off = rowoff + (uint32_t)(((k >> 3) ^ rs) << 4) + (uint32_t)((k & 7) << 1);
                *(uint2*)(smem + M2_AHI + off) = make_uint2(pkbf(v.x, v.y), pkbf(v.z, v.w));
                *(uint2*)(smem + M2_ALO + off) = make_uint2(pkbf(bflo(v.x), bflo(v.y)),
                                                            pkbf(bflo(v.z), bflo(v.w)));
            }
        }
        __syncthreads();
        int tn = t + gridDim.x;
        if (tn < T64) do_prefetch(tn << 6);

        float d[2][4][4];
        #pragma unroll
        for (int m = 0; m < 2; ++m)
            #pragma unroll
            for (int nb = 0; nb < 4; ++nb)
                #pragma unroll
                for (int e = 0; e < 4; ++e) d[m][nb][e] = 0.f;

        #pragma unroll 4
        for (int ks = 0; ks < 8; ++ks) {
            uint32_t ach = (uint32_t)((((ks << 1) + kp) ^ l7) << 4);
            uint32_t ahi0[4], ahi1[4], alo0[4], alo1[4];
            ldmA(ahi0, aRowHi + ach);
            ldmA(ahi1, aRowHi + 4096 + ach);
            ldmA(alo0, aRowLo + ach);
            ldmA(alo1, aRowLo + 4096 + ach);
            uint32_t bks = (uint32_t)ks << 12;
            uint32_t bh0[4], bh1[4], bl0[4], bl1[4];
            ldmBT(bh0, bHiBase + bks + bch0);
            ldmBT(bh1, bHiBase + bks + bch1);
            ldmBT(bl0, bLoBase + bks + bch0);
            ldmBT(bl1, bLoBase + bks + bch1);
            mmabf(d[0][0], ahi0, bh0); mmabf(d[0][1], ahi0, bh0 + 2);
            mmabf(d[0][2], ahi0, bh1); mmabf(d[0][3], ahi0, bh1 + 2);
            mmabf(d[1][0], ahi1, bh0); mmabf(d[1][1], ahi1, bh0 + 2);
            mmabf(d[1][2], ahi1, bh1); mmabf(d[1][3], ahi1, bh1 + 2);
            mmabf(d[0][0], ahi0, bl0); mmabf(d[0][1], ahi0, bl0 + 2);
            mmabf(d[0][2], ahi0, bl1); mmabf(d[0][3], ahi0, bl1 + 2);
            mmabf(d[1][0], ahi1, bl0); mmabf(d[1][1], ahi1, bl0 + 2);
            mmabf(d[1][2], ahi1, bl1); mmabf(d[1][3], ahi1, bl1 + 2);
            mmabf(d[0][0], alo0, bh0); mmabf(d[0][1], alo0, bh0 + 2);
            mmabf(d[0][2], alo0, bh1); mmabf(d[0][3], alo0, bh1 + 2);
            mmabf(d[1][0], alo1, bh0); mmabf(d[1][1], alo1, bh0 + 2);
            mmabf(d[1][2], alo1, bh1); mmabf(d[1][3], alo1, bh1 + 2);
        }

        #pragma unroll
        for (int m = 0; m < 2; ++m) {
            int row0 = t0 + rbase + (m << 4) + g;
            int row1 = row0 + 8;
            #pragma unroll
            for (int nb = 0; nb < 4; ++nb) {
                int col = nbase + (tq << 1) + (nb << 3);
                #pragma unroll
                for (int j = 0; j < 2; ++j) {
                    int c = col + j;
                    if (c < 40) {
                        if (row0 < NDV) out[(size_t)row0 * OD + c] = d[m][nb][j] + bias[c];
                        if (row1 < NDV) out[(size_t)row1 * OD + c] = d[m][nb][j + 2] + bias[c];
                    } else if (c < 80) {
                        if (row0 < NDV) g_p[(size_t)row0 * OD + c - 40] = d[m][nb][j];
                        if (row1 < NDV) g_p[(size_t)row1 * OD + c - 40] = d[m][nb][j + 2];
                    }
                }
            }
        }
    }
}

// CSR layer-2 neighbor mean: 10 threads per node, 4-edge-batched p reads
__global__ void k_edge2csr(float* __restrict__ out) {
    int idx = blockIdx.x * blockDim.x + threadIdx.x;
    if (idx >= NDV * 10) return;
    int n = idx / 10, c4 = idx - n * 10;
    int b = g_rowstart[n], e = g_rowstart[n + 1];
    float4 acc = make_float4(0.f, 0.f, 0.f, 0.f);
    int i = b;
    for (; i + 4 <= e; i += 4) {
        int s0 = g_csr_src[i], s1 = g_csr_src[i + 1];
        int s2 = g_csr_src[i + 2], s3 = g_csr_src[i + 3];
        float4 v0 = *(const float4*)(g_p + (size_t)s0 * OD + c4 * 4);
        float4 v1 = *(const float4*)(g_p + (size_t)s1 * OD + c4 * 4);
        float4 v2 = *(const float4*)(g_p + (size_t)s2 * OD + c4 * 4);
        float4 v3 = *(const float4*)(g_p + (size_t)s3 * OD + c4 * 4);
        acc.x += (v0.x + v1.x) + (v2.x + v3.x);
        acc.y += (v0.y + v1.y) + (v2.y + v3.y);
        acc.z += (v0.z + v1.z) + (v2.z + v3.z);
        acc.w += (v0.w + v1.w) + (v2.w + v3.w);
    }
    for (; i < e; ++i) {
        int s = g_csr_src[i];
        float4 v = *(const float4*)(g_p + (size_t)s * OD + c4 * 4);
        acc.x += v.x; acc.y += v.y; acc.z += v.z; acc.w += v.w;
    }
    float iv = 1.f / fmaxf((float)(e - b), 1.f);
    float* o = out + (size_t)n * OD + c4 * 4;
    float4 cur = *(float4*)o;
    cur.x += acc.x * iv; cur.y += acc.y * iv;
    cur.z += acc.z * iv; cur.w += acc.w * iv;
    *(float4*)o = cur;
}

// ---------------- host launcher ------------------------------------------------
extern "C" void kernel_launch(void* const* d_in, const int* in_sizes, int n_in,
                              void* d_out, int out_size) {
    const float* feat = (const float*)d_in[0];
    const int*   src  = (const int*)d_in[1];
    const int*   dst  = (const int*)d_in[2];
    const float* Ws0 = (const float*)d_in[3];
    const float* Wn0 = (const float*)d_in[4];
    const float* ga0 = (const float*)d_in[5];
    const float* be0 = (const float*)d_in[6];
    const float* Ws1 = (const float*)d_in[7];
    const float* Wn1 = (const float*)d_in[8];
    const float* ga1 = (const float*)d_in[9];
    const float* be1 = (const float*)d_in[10];
    const float* Ws2 = (const float*)d_in[11];
    const float* Wn2 = (const float*)d_in[12];
    const float* b2  = (const float*)d_in[13];
    float* out = (float*)d_out;

    cudaFuncSetAttribute(k_gemm01mma, cudaFuncAttributeMaxDynamicSharedMemorySize, MM_TOT);
    cudaFuncSetAttribute(k_gemm2mma,  cudaFuncAttributeMaxDynamicSharedMemorySize, M2_TOT);

    const int TB = 256;
    // CSR build
    k_zdegi<<<(NDV + TB - 1) / TB, TB>>>();
    k_degi<<<(NE + TB - 1) / TB, TB>>>(dst);
    k_scan1<<<SCB, 1024>>>();
    k_scan3<<<SCB, 1024>>>();
    k_scatter<<<(NE + TB - 1) / TB, TB>>>(src, dst);

    // ---- layer 0 ----
    k_aggcsr<<<(NDV * 32 + TB - 1) / TB, TB>>>(feat, 0);
    k_gemm01mma<<<148, 256, MM_TOT>>>(feat, 0, Ws0, Wn0);
    k_bnfin<<<1, 128>>>(ga0, be0);
    k_apply<<<(NDV * 32 + TB - 1) / TB, TB>>>();

    // ---- layer 1 ----
    k_aggcsr<<<(NDV * 32 + TB - 1) / TB, TB>>>(nullptr, 1);
    k_gemm01mma<<<148, 256, MM_TOT>>>(nullptr, 1, Ws1, Wn1);
    k_bnfin<<<1, 128>>>(ga1, be1);

    // ---- layer 2 (BN1+ReLU fused into gemm2 staging; second k_apply deleted) --
    k_gemm2mma<<<148, 256, M2_TOT>>>(Ws2, Wn2, b2, out);
    k_edge2csr<<<(NDV * 10 + TB - 1) / TB, TB>>>(out);

    (void)in_sizes; (void)n_in; (void)out_size;
}